// round 9
// baseline (speedup 1.0000x reference)
#include <cuda_runtime.h>

// Problem constants (fixed by the reference)
#define B       32
#define N       2048
#define OUTD    100
#define JSPLITS 16
#define JCHUNK  (N / JSPLITS)        // 128
#define BPG     4                    // batch rows per block (W register reuse)
#define BGROUPS (B / BPG)            // 8
#define GRID    (JSPLITS * BGROUPS)  // 128 blocks
#define NT      512
#define NW      16
#define J_PER_WARP (JCHUNK / NW)     // 8

// out[b,o] = sum_j rem[b,j] * W[j,o]
// rem[b,j] = (q[b,j] - float(N*c[b,j] + S_b))^2, c = (int)q, S_b = sum_j c[b,j]
// Exact vs reference: all integer partials < 2^24, so the reference's fp32
// reduce of the [N,N] broadcast equals the int32 closed form bit-for-bit.

__device__ float        g_partial[JSPLITS][B][OUTD];
__device__ unsigned int g_count[BGROUPS];            // zero-initialized

__global__ __launch_bounds__(NT, 1)
void fused_rowstat_gemv_kernel(const float* __restrict__ q,
                               const float* __restrict__ W,
                               float* __restrict__ out)
{
    __shared__ float4 rem4[BPG][JCHUNK / 4];     // 2 KB
    __shared__ float  part_sh[NW][BPG * OUTD];   // 25.6 KB
    __shared__ int    qsum[NW];
    __shared__ bool   is_last;

    const int tid  = threadIdx.x;
    const int wid  = tid >> 5;
    const int lane = tid & 31;
    const int s    = blockIdx.x & (JSPLITS - 1);   // j-split index
    const int bg   = blockIdx.x >> 4;              // batch-group index
    const int j0   = s * JCHUNK;

    // ---- Prefetch W into registers (block-index-dependent only). These
    //      8 independent LDG.128 retire behind the q-load/reduce phases. ----
    const int g  = lane;                 // output group: o = 4g..4g+3 (g<25)
    const int jw = wid * J_PER_WARP;
    float4 w4[J_PER_WARP];
    if (g < 25) {
        const float* Wg = W + (size_t)(j0 + jw) * OUTD + g * 4;
        #pragma unroll
        for (int jj = 0; jj < J_PER_WARP; ++jj)
            w4[jj] = *reinterpret_cast<const float4*>(Wg + jj * OUTD);
    }

    // ---- Phase 1: int row-sums for the 4 rows (4 warps per row), and keep
    //      the float4 that belongs to this block's j-chunk in a register. ----
    const int r       = wid >> 2;                  // row within group
    const int quarter = wid & 3;
    const int i_need  = s >> 2;                    // unroll step holding chunk s
    const bool owns_chunk = (quarter == (s & 3));
    float4 vkeep;
    {
        const float4* q4 = reinterpret_cast<const float4*>(q + (bg * BPG + r) * N);
        const int t = quarter * 32 + lane;         // 0..127
        int ss = 0;
        #pragma unroll
        for (int i = 0; i < 4; ++i) {
            float4 v = q4[t + 128 * i];
            ss += (int)v.x + (int)v.y + (int)v.z + (int)v.w;
            if (i == i_need) vkeep = v;
        }
        #pragma unroll
        for (int o = 16; o > 0; o >>= 1) ss += __shfl_xor_sync(0xFFFFFFFFu, ss, o);
        if (lane == 0) qsum[wid] = ss;
    }
    __syncthreads();

    // ---- Phase 2: rem chunk straight from registers; owner warps read the
    //      four per-warp sums via broadcast LDS (no extra barrier round). ----
    if (owns_chunk) {
        const int   S = qsum[4*r] + qsum[4*r+1] + qsum[4*r+2] + qsum[4*r+3];
        const float4 v = vkeep;
        int   c0 = (int)v.x, c1 = (int)v.y, c2 = (int)v.z, c3 = (int)v.w;
        float d0 = v.x - (float)(N * c0 + S);
        float d1 = v.y - (float)(N * c1 + S);
        float d2 = v.z - (float)(N * c2 + S);
        float d3 = v.w - (float)(N * c3 + S);
        rem4[r][lane] = make_float4(d0*d0, d1*d1, d2*d2, d3*d3);
    }
    __syncthreads();

    // ---- Phase 3: GEMV on registers + smem broadcast ----
    if (g < 25) {
        const float* rem = reinterpret_cast<const float*>(&rem4[0][0]);
        float acc[BPG][4];
        #pragma unroll
        for (int rr = 0; rr < BPG; ++rr)
            acc[rr][0] = acc[rr][1] = acc[rr][2] = acc[rr][3] = 0.f;
        #pragma unroll
        for (int jj = 0; jj < J_PER_WARP; ++jj) {
            #pragma unroll
            for (int rr = 0; rr < BPG; ++rr) {
                float rv = rem[rr * JCHUNK + jw + jj];
                acc[rr][0] = fmaf(rv, w4[jj].x, acc[rr][0]);
                acc[rr][1] = fmaf(rv, w4[jj].y, acc[rr][1]);
                acc[rr][2] = fmaf(rv, w4[jj].z, acc[rr][2]);
                acc[rr][3] = fmaf(rv, w4[jj].w, acc[rr][3]);
            }
        }
        #pragma unroll
        for (int rr = 0; rr < BPG; ++rr)
            *reinterpret_cast<float4*>(&part_sh[wid][rr * OUTD + g * 4]) =
                make_float4(acc[rr][0], acc[rr][1], acc[rr][2], acc[rr][3]);
    }
    __syncthreads();

    // ---- Phase 4: reduce 16 warps, emit split-K partial ----
    if (tid < BPG * OUTD) {                        // 400 of 512 threads
        float ssum = 0.f;
        #pragma unroll
        for (int w = 0; w < NW; ++w) ssum += part_sh[w][tid];
        const int rr = tid / OUTD;
        const int o  = tid - rr * OUTD;
        g_partial[s][bg * BPG + rr][o] = ssum;
    }
    __threadfence();
    __syncthreads();

    // ---- Phase 5: per-bgroup last block reduces its 16 splits ----
    if (tid == 0) {
        unsigned old = atomicAdd(&g_count[bg], 1u);
        is_last = (old == JSPLITS - 1);
        if (is_last) g_count[bg] = 0;              // self-reset for graph replay
    }
    __syncthreads();

    if (is_last && tid < BPG * OUTD) {
        const int rr = tid / OUTD;
        const int o  = tid - rr * OUTD;
        const int b  = bg * BPG + rr;
        // 16 independent loads issued back-to-back, then a pairwise tree sum
        // (fixed order -> deterministic, one memory roundtrip).
        float v[JSPLITS];
        #pragma unroll
        for (int sp = 0; sp < JSPLITS; ++sp) v[sp] = g_partial[sp][b][o];
        #pragma unroll
        for (int st = 1; st < JSPLITS; st <<= 1)
            #pragma unroll
            for (int i = 0; i < JSPLITS; i += 2 * st) v[i] += v[i + st];
        out[b * OUTD + o] = v[0];
    }
}

extern "C" void kernel_launch(void* const* d_in, const int* in_sizes, int n_in,
                              void* d_out, int out_size)
{
    const float* q = (const float*)d_in[0];   // [32, 2048] f32
    const float* W = (const float*)d_in[1];   // [2048, 100] f32
    float* out = (float*)d_out;               // [32, 100] f32
    (void)in_sizes; (void)n_in; (void)out_size;

    fused_rowstat_gemv_kernel<<<GRID, NT>>>(q, W, out);
}